// round 1
// baseline (speedup 1.0000x reference)
#include <cuda_runtime.h>

#define NQ 12
#define DIM 4096
#define NLAYERS 3
#define NGATES (NLAYERS * NQ)   // 36
#define TPB 512
#define APT 8    // amplitudes per thread (DIM/TPB)
#define PPT 4    // pairs per thread (DIM/2/TPB)

// Fused gate matrices: 36 gates x 8 floats (u00r,u00i,u01r,u01i,u10r,u10i,u11r,u11i)
__device__ float g_gates[NGATES * 8];

// ---------------------------------------------------------------------------
// Prep: fuse RZ(c)*RY(b)*RX(a) per (layer,qubit) into one 2x2 complex matrix.
// params layout: [layer][qubit][rx,ry,rz] flattened -> gate g uses params[3g..3g+2]
// ---------------------------------------------------------------------------
__global__ void prep_gates(const float* __restrict__ params) {
    int g = blockIdx.x * blockDim.x + threadIdx.x;
    if (g >= NGATES) return;
    float a = params[3 * g + 0] * 0.5f;
    float b = params[3 * g + 1] * 0.5f;
    float c = params[3 * g + 2] * 0.5f;
    float ca = cosf(a), sa = sinf(a);
    float cb = cosf(b), sb = sinf(b);
    float cc = cosf(c), sc = sinf(c);
    // M = RY * RX
    //   RX = [[ca, -i sa], [-i sa, ca]]
    //   RY = [[cb, -sb], [sb, cb]]
    float m00r = cb * ca, m00i = sb * sa;
    float m01r = -sb * ca, m01i = -cb * sa;
    float m10r = sb * ca, m10i = -cb * sa;
    float m11r = cb * ca, m11i = -sb * sa;
    // G = RZ * M ; RZ = diag(e^{-ic}, e^{+ic}) (half-angle already applied)
    // row0 scaled by (cc, -sc), row1 by (cc, +sc)
    float* o = &g_gates[g * 8];
    o[0] = cc * m00r + sc * m00i;  o[1] = cc * m00i - sc * m00r;
    o[2] = cc * m01r + sc * m01i;  o[3] = cc * m01i - sc * m01r;
    o[4] = cc * m10r - sc * m10i;  o[5] = cc * m10i + sc * m10r;
    o[6] = cc * m11r - sc * m11i;  o[7] = cc * m11i + sc * m11r;
}

// ---------------------------------------------------------------------------
// Main: one CTA per batch element. State in SMEM (split re/im).
// Qubit q lives on bit (11-q) of the flattened index (C-order reshape).
// ---------------------------------------------------------------------------
__global__ __launch_bounds__(TPB, 4) void qsim_kernel(
    const float* __restrict__ x, float* __restrict__ out) {
    __shared__ float sre[DIM];
    __shared__ float sim[DIM];
    __shared__ float sG[NGATES * 8];
    __shared__ float sAcc[NQ];
    __shared__ float sRed[TPB / 32];

    const int tid = threadIdx.x;
    const int bid = blockIdx.x;
    const float* xb = x + (size_t)bid * DIM;

    if (tid < NGATES * 8) sG[tid] = g_gates[tid];
    if (tid < NQ) sAcc[tid] = 0.0f;

    // ---- load + sum of squares ----
    float ss = 0.0f;
#pragma unroll
    for (int k = 0; k < APT; k++) {
        int i = k * TPB + tid;
        float v = xb[i];
        sre[i] = v;
        sim[i] = 0.0f;
        ss += v * v;
    }
#pragma unroll
    for (int o = 16; o; o >>= 1) ss += __shfl_xor_sync(0xffffffffu, ss, o);
    if ((tid & 31) == 0) sRed[tid >> 5] = ss;
    __syncthreads();
    ss = 0.0f;
#pragma unroll
    for (int w = 0; w < TPB / 32; w++) ss += sRed[w];
    const float inv_norm = rsqrtf(ss);
#pragma unroll
    for (int k = 0; k < APT; k++) {
        int i = k * TPB + tid;
        sre[i] *= inv_norm;   // sim already 0
    }

    // ---- precompute CNOT-ring permutation sigma for this thread's amps ----
    // final[i] = pre[sigma(i)], sigma = f_11 ∘ ... ∘ f_0 applied innermost-last:
    // j=i; for g = 11..0: j ^= ((j>>bc_g)&1) << bt_g   (bc=11-g, bt=11-((g+1)%12))
    int sig[APT];
#pragma unroll
    for (int k = 0; k < APT; k++) {
        int j = k * TPB + tid;
#pragma unroll
        for (int g = NQ - 1; g >= 0; g--) {
            const int bc = 11 - g;
            const int bt = 11 - ((g + 1) % NQ);
            j ^= ((j >> bc) & 1) << bt;
        }
        sig[k] = j;
    }

    // ---- circuit ----
    for (int layer = 0; layer < NLAYERS; layer++) {
        for (int q = 0; q < NQ; q++) {
            const int bpos = 11 - q;
            const float* G = &sG[(layer * NQ + q) * 8];
            const float u00r = G[0], u00i = G[1], u01r = G[2], u01i = G[3];
            const float u10r = G[4], u10i = G[5], u11r = G[6], u11i = G[7];
            const int lo_mask = (1 << bpos) - 1;
            __syncthreads();
#pragma unroll
            for (int k = 0; k < PPT; k++) {
                int p = k * TPB + tid;
                int i0 = ((p >> bpos) << (bpos + 1)) | (p & lo_mask);
                int i1 = i0 | (1 << bpos);
                float a0r = sre[i0], a0i = sim[i0];
                float a1r = sre[i1], a1i = sim[i1];
                float n0r = u00r * a0r - u00i * a0i + u01r * a1r - u01i * a1i;
                float n0i = u00r * a0i + u00i * a0r + u01r * a1i + u01i * a1r;
                float n1r = u10r * a0r - u10i * a0i + u11r * a1r - u11i * a1i;
                float n1i = u10r * a0i + u10i * a0r + u11r * a1i + u11i * a1r;
                sre[i0] = n0r; sim[i0] = n0i;
                sre[i1] = n1r; sim[i1] = n1i;
            }
        }
        // CNOT ring as one permutation: gather to regs, sync, scatter
        __syncthreads();
        float tr[APT], ti[APT];
#pragma unroll
        for (int k = 0; k < APT; k++) {
            tr[k] = sre[sig[k]];
            ti[k] = sim[sig[k]];
        }
        __syncthreads();
#pragma unroll
        for (int k = 0; k < APT; k++) {
            int i = k * TPB + tid;
            sre[i] = tr[k];
            sim[i] = ti[k];
        }
    }

    // ---- expectations <Z_q> = sum_i p_i * (1 - 2*bit(i, 11-q)) ----
    __syncthreads();
    float acc[NQ];
#pragma unroll
    for (int q = 0; q < NQ; q++) acc[q] = 0.0f;
#pragma unroll
    for (int k = 0; k < APT; k++) {
        int i = k * TPB + tid;
        float r = sre[i], m = sim[i];
        float p = r * r + m * m;
#pragma unroll
        for (int q = 0; q < NQ; q++) {
            const int bb = 11 - q;
            acc[q] += ((i >> bb) & 1) ? -p : p;
        }
    }
#pragma unroll
    for (int q = 0; q < NQ; q++) {
#pragma unroll
        for (int o = 16; o; o >>= 1)
            acc[q] += __shfl_xor_sync(0xffffffffu, acc[q], o);
    }
    if ((tid & 31) == 0) {
#pragma unroll
        for (int q = 0; q < NQ; q++) atomicAdd(&sAcc[q], acc[q]);
    }
    __syncthreads();
    if (tid < NQ) out[(size_t)bid * NQ + tid] = sAcc[tid];
}

extern "C" void kernel_launch(void* const* d_in, const int* in_sizes, int n_in,
                              void* d_out, int out_size) {
    const float* x = (const float*)d_in[0];       // (8192, 4096) float32
    const float* params = (const float*)d_in[1];  // (108,) float32
    float* out = (float*)d_out;                   // (8192, 12) float32
    const int batch = in_sizes[0] / DIM;

    prep_gates<<<1, 64>>>(params);
    qsim_kernel<<<batch, TPB>>>(x, out);
}

// round 2
// speedup vs baseline: 1.0537x; 1.0537x over previous
#include <cuda_runtime.h>

#define NQ 12
#define DIM 4096
#define NLAYERS 3
#define NGATES (NLAYERS * NQ)   // 36
#define TPB 512
#define RPT 8                   // register amplitudes per thread
#define STRIDE 9                // padded smem row stride (floats)
#define BUF (TPB * STRIDE)      // 4608 floats per component

// Fused gate matrices: 36 gates x 8 floats (u00r,u00i,u01r,u01i,u10r,u10i,u11r,u11i)
__device__ float g_gates[NGATES * 8];

// ---------------------------------------------------------------------------
// Prep: fuse RZ(c)*RY(b)*RX(a) per (layer,qubit) into one 2x2 complex matrix.
// ---------------------------------------------------------------------------
__global__ void prep_gates(const float* __restrict__ params) {
    int g = blockIdx.x * blockDim.x + threadIdx.x;
    if (g >= NGATES) return;
    float a = params[3 * g + 0] * 0.5f;
    float b = params[3 * g + 1] * 0.5f;
    float c = params[3 * g + 2] * 0.5f;
    float ca = cosf(a), sa = sinf(a);
    float cb = cosf(b), sb = sinf(b);
    float cc = cosf(c), sc = sinf(c);
    float m00r = cb * ca, m00i = sb * sa;
    float m01r = -sb * ca, m01i = -cb * sa;
    float m10r = sb * ca, m10i = -cb * sa;
    float m11r = cb * ca, m11i = -sb * sa;
    float* o = &g_gates[g * 8];
    o[0] = cc * m00r + sc * m00i;  o[1] = cc * m00i - sc * m00r;
    o[2] = cc * m01r + sc * m01i;  o[3] = cc * m01i - sc * m01r;
    o[4] = cc * m10r - sc * m10i;  o[5] = cc * m10i + sc * m10r;
    o[6] = cc * m11r - sc * m11i;  o[7] = cc * m11i + sc * m11r;
}

// Apply the 3 gates whose qubit bits are the register-index bits (bit2,1,0 of r).
__device__ __forceinline__ void apply3(float vr[RPT], float vi[RPT],
                                       const float* __restrict__ sG, int gbase) {
#pragma unroll
    for (int qq = 0; qq < 3; qq++) {
        const float* G = &sG[(gbase + qq) * 8];
        const float u00r = G[0], u00i = G[1], u01r = G[2], u01i = G[3];
        const float u10r = G[4], u10i = G[5], u11r = G[6], u11i = G[7];
        const int mb = 4 >> qq;
#pragma unroll
        for (int r = 0; r < RPT; r++) {
            if (!(r & mb)) {
                const int r1 = r | mb;
                float a0r = vr[r],  a0i = vi[r];
                float a1r = vr[r1], a1i = vi[r1];
                vr[r]  = u00r * a0r - u00i * a0i + u01r * a1r - u01i * a1i;
                vi[r]  = u00r * a0i + u00i * a0r + u01r * a1i + u01i * a1r;
                vr[r1] = u10r * a0r - u10i * a0i + u11r * a1r - u11i * a1i;
                vi[r1] = u10r * a0i + u10i * a0r + u11r * a1i + u11i * a1r;
            }
        }
    }
}

// ---------------------------------------------------------------------------
// Main: one CTA per batch element. State lives in registers (8 cplx/thread).
// Layouts (which 3 index bits select the register slot r):
//   L0: r={b11,b10,b9}  t = b8..b0
//   L1: r={b8,b7,b6}    t = [b11 b10 b9 | b5..b0]
//   L2: r={b5,b4,b3}    t = [b11..b6 | b2 b1 b0]
//   L3: r={b2,b1,b0}    t = b11..b3
// ---------------------------------------------------------------------------
__global__ __launch_bounds__(TPB, 2) void qsim_kernel(
    const float* __restrict__ x, float* __restrict__ out) {
    __shared__ float shr[BUF];
    __shared__ float shi[BUF];
    __shared__ float sG[NGATES * 8];
    __shared__ float sRed[TPB / 32];
    __shared__ float sAcc[NQ];

    const int tid = threadIdx.x;
    const int bid = blockIdx.x;
    const float* xb = x + (size_t)bid * DIM;

    if (tid < NGATES * 8) sG[tid] = g_gates[tid];
    if (tid < NQ) sAcc[tid] = 0.0f;

    // ---- load into L0 registers + normalize ----
    float vr[RPT], vi[RPT];
    float ss = 0.0f;
#pragma unroll
    for (int r = 0; r < RPT; r++) {
        float v = xb[r * TPB + tid];
        vr[r] = v;
        vi[r] = 0.0f;
        ss += v * v;
    }
#pragma unroll
    for (int o = 16; o; o >>= 1) ss += __shfl_xor_sync(0xffffffffu, ss, o);
    if ((tid & 31) == 0) sRed[tid >> 5] = ss;
    __syncthreads();
    ss = 0.0f;
#pragma unroll
    for (int w = 0; w < TPB / 32; w++) ss += sRed[w];
    const float inv_norm = rsqrtf(ss);
#pragma unroll
    for (int r = 0; r < RPT; r++) vr[r] *= inv_norm;

    // ---- loop-invariant exchange address bases ----
    // X1 write (L0 value i=(r<<9)|t): t1=((i>>9)<<6)|(i&63), r1=(i>>6)&7
    const int base1 = (tid & 63) * STRIDE + ((tid >> 6) & 7);          // + r*576
    // X2 write (L1): t2=((i>>6)<<3)|(i&7), r2=(i>>3)&7
    const int base2 = (((tid >> 6) << 6) | (tid & 7)) * STRIDE + ((tid >> 3) & 7); // + r*72
    // X3 write (L2): t3=i>>3, r3=i&7
    const int base3 = (tid >> 3) * (8 * STRIDE) + (tid & 7);           // + r*9
    // X4 read (sigma gather): new L0 value at i=(r<<9)|tid is old[m(i)]
    int addr4[RPT];
#pragma unroll
    for (int r = 0; r < RPT; r++) {
        int j = (r << 9) | tid;
#pragma unroll
        for (int g = NQ - 1; g >= 0; g--) {
            const int bc = 11 - g;
            const int bt = 11 - ((g + 1) % NQ);
            j ^= ((j >> bc) & 1) << bt;
        }
        addr4[r] = (j >> 3) * STRIDE + (j & 7);
    }

    // ---- circuit ----
    for (int layer = 0; layer < NLAYERS; layer++) {
        const int gbase = layer * NQ;

        // gates q0,q1,q2 (bits 11,10,9) in L0 registers
        apply3(vr, vi, sG, gbase + 0);
        // X1: L0 -> L1
#pragma unroll
        for (int r = 0; r < RPT; r++) {
            int a = base1 + r * (64 * STRIDE);
            shr[a] = vr[r]; shi[a] = vi[r];
        }
        __syncthreads();
#pragma unroll
        for (int r = 0; r < RPT; r++) {
            int a = tid * STRIDE + r;
            vr[r] = shr[a]; vi[r] = shi[a];
        }
        __syncthreads();

        // gates q3,q4,q5 (bits 8,7,6)
        apply3(vr, vi, sG, gbase + 3);
        // X2: L1 -> L2
#pragma unroll
        for (int r = 0; r < RPT; r++) {
            int a = base2 + r * (8 * STRIDE);
            shr[a] = vr[r]; shi[a] = vi[r];
        }
        __syncthreads();
#pragma unroll
        for (int r = 0; r < RPT; r++) {
            int a = tid * STRIDE + r;
            vr[r] = shr[a]; vi[r] = shi[a];
        }
        __syncthreads();

        // gates q6,q7,q8 (bits 5,4,3)
        apply3(vr, vi, sG, gbase + 6);
        // X3: L2 -> L3
#pragma unroll
        for (int r = 0; r < RPT; r++) {
            int a = base3 + r * STRIDE;
            shr[a] = vr[r]; shi[a] = vi[r];
        }
        __syncthreads();
#pragma unroll
        for (int r = 0; r < RPT; r++) {
            int a = tid * STRIDE + r;
            vr[r] = shr[a]; vi[r] = shi[a];
        }
        __syncthreads();

        // gates q9,q10,q11 (bits 2,1,0)
        apply3(vr, vi, sG, gbase + 9);
        // X4: L3 -> L0 with CNOT-ring permutation folded into the read
#pragma unroll
        for (int r = 0; r < RPT; r++) {
            int a = tid * STRIDE + r;            // canonical L3 write: j=(tid<<3)|r
            shr[a] = vr[r]; shi[a] = vi[r];
        }
        __syncthreads();
#pragma unroll
        for (int r = 0; r < RPT; r++) {
            vr[r] = shr[addr4[r]]; vi[r] = shi[addr4[r]];
        }
        __syncthreads();
    }

    // ---- expectations <Z_q> from L0 registers ----
    float acc[NQ];
#pragma unroll
    for (int q = 0; q < NQ; q++) acc[q] = 0.0f;
#pragma unroll
    for (int r = 0; r < RPT; r++) {
        float p = vr[r] * vr[r] + vi[r] * vi[r];
        const int i = (r << 9) | tid;
#pragma unroll
        for (int q = 0; q < NQ; q++) {
            acc[q] += ((i >> (11 - q)) & 1) ? -p : p;
        }
    }
#pragma unroll
    for (int q = 0; q < NQ; q++) {
#pragma unroll
        for (int o = 16; o; o >>= 1)
            acc[q] += __shfl_xor_sync(0xffffffffu, acc[q], o);
    }
    if ((tid & 31) == 0) {
#pragma unroll
        for (int q = 0; q < NQ; q++) atomicAdd(&sAcc[q], acc[q]);
    }
    __syncthreads();
    if (tid < NQ) out[(size_t)bid * NQ + tid] = sAcc[tid];
}

extern "C" void kernel_launch(void* const* d_in, const int* in_sizes, int n_in,
                              void* d_out, int out_size) {
    const float* x = (const float*)d_in[0];       // (8192, 4096) float32
    const float* params = (const float*)d_in[1];  // (108,) float32
    float* out = (float*)d_out;                   // (8192, 12) float32
    const int batch = in_sizes[0] / DIM;

    prep_gates<<<1, 64>>>(params);
    qsim_kernel<<<batch, TPB>>>(x, out);
}

// round 4
// speedup vs baseline: 1.6062x; 1.5243x over previous
#include <cuda_runtime.h>

#define NQ 12
#define DIM 4096
#define NLAYERS 3
#define NGATES (NLAYERS * NQ)   // 36
#define TPB 512
#define RPT 8                   // register amplitudes per thread (per packed pair)
#define STRIDE 9                // padded smem row stride (in 8-byte units)
#define BUF (TPB * STRIDE)      // 4608 u64 per component per buffer

typedef unsigned long long u64;

// Pre-packed gate coefficients: 36 gates x 12 float2 (duplicated / negated-duplicated)
__device__ float2 g_gates2[NGATES * 12];

// ---------------- f32x2 helpers (sm_103a packed fp32) ----------------
__device__ __forceinline__ u64 pk2(float x, float y) {
    u64 r; asm("mov.b64 %0, {%1, %2};" : "=l"(r) : "f"(x), "f"(y)); return r;
}
__device__ __forceinline__ void unpk2(u64 a, float& x, float& y) {
    asm("mov.b64 {%0, %1}, %2;" : "=f"(x), "=f"(y) : "l"(a));
}
__device__ __forceinline__ u64 f2fma(u64 a, u64 b, u64 c) {
    u64 d; asm("fma.rn.f32x2 %0, %1, %2, %3;" : "=l"(d) : "l"(a), "l"(b), "l"(c)); return d;
}
__device__ __forceinline__ u64 f2mul(u64 a, u64 b) {
    u64 d; asm("mul.rn.f32x2 %0, %1, %2;" : "=l"(d) : "l"(a), "l"(b)); return d;
}
__device__ __forceinline__ u64 f2add(u64 a, u64 b) {
    u64 d; asm("add.rn.f32x2 %0, %1, %2;" : "=l"(d) : "l"(a), "l"(b)); return d;
}

// ---------------------------------------------------------------------------
// Prep: fuse RZ*RY*RX per gate; emit 12 duplicated-packed coefficient pairs.
// Order: 0:(u00r) 1:(-u00i) 2:(u01r) 3:(-u01i) 4:(u00i) 5:(u01i)
//        6:(u10r) 7:(-u10i) 8:(u11r) 9:(-u11i) 10:(u10i) 11:(u11i)
// ---------------------------------------------------------------------------
__global__ void prep_gates(const float* __restrict__ params) {
    int g = blockIdx.x * blockDim.x + threadIdx.x;
    if (g >= NGATES) return;
    float a = params[3 * g + 0] * 0.5f;
    float b = params[3 * g + 1] * 0.5f;
    float c = params[3 * g + 2] * 0.5f;
    float ca = cosf(a), sa = sinf(a);
    float cb = cosf(b), sb = sinf(b);
    float cc = cosf(c), sc = sinf(c);
    float m00r = cb * ca, m00i = sb * sa;
    float m01r = -sb * ca, m01i = -cb * sa;
    float m10r = sb * ca, m10i = -cb * sa;
    float m11r = cb * ca, m11i = -sb * sa;
    float u00r = cc * m00r + sc * m00i, u00i = cc * m00i - sc * m00r;
    float u01r = cc * m01r + sc * m01i, u01i = cc * m01i - sc * m01r;
    float u10r = cc * m10r - sc * m10i, u10i = cc * m10i + sc * m10r;
    float u11r = cc * m11r - sc * m11i, u11i = cc * m11i + sc * m11r;
    float2* o = &g_gates2[g * 12];
    o[0]  = make_float2(u00r, u00r);
    o[1]  = make_float2(-u00i, -u00i);
    o[2]  = make_float2(u01r, u01r);
    o[3]  = make_float2(-u01i, -u01i);
    o[4]  = make_float2(u00i, u00i);
    o[5]  = make_float2(u01i, u01i);
    o[6]  = make_float2(u10r, u10r);
    o[7]  = make_float2(-u10i, -u10i);
    o[8]  = make_float2(u11r, u11r);
    o[9]  = make_float2(-u11i, -u11i);
    o[10] = make_float2(u10i, u10i);
    o[11] = make_float2(u11i, u11i);
}

// Apply 3 gates on the register-index bits (bit2,1,0 of r) for a packed batch-pair.
__device__ __forceinline__ void apply3(u64 vre[RPT], u64 vim[RPT],
                                       const u64* __restrict__ sG2, int gbase) {
#pragma unroll
    for (int qq = 0; qq < 3; qq++) {
        const u64* C = &sG2[(gbase + qq) * 12];
        const u64 c0 = C[0], c1 = C[1], c2 = C[2], c3 = C[3], c4 = C[4], c5 = C[5];
        const u64 c6 = C[6], c7 = C[7], c8 = C[8], c9 = C[9], c10 = C[10], c11 = C[11];
        const int mb = 4 >> qq;
#pragma unroll
        for (int r = 0; r < RPT; r++) {
            if (!(r & mb)) {
                const int r1 = r | mb;
                u64 a0re = vre[r],  a0im = vim[r];
                u64 a1re = vre[r1], a1im = vim[r1];
                u64 n0re = f2fma(c0, a0re, f2fma(c1, a0im, f2fma(c2, a1re, f2mul(c3, a1im))));
                u64 n0im = f2fma(c4, a0re, f2fma(c0, a0im, f2fma(c5, a1re, f2mul(c2, a1im))));
                u64 n1re = f2fma(c6, a0re, f2fma(c7, a0im, f2fma(c8, a1re, f2mul(c9, a1im))));
                u64 n1im = f2fma(c10, a0re, f2fma(c6, a0im, f2fma(c11, a1re, f2mul(c8, a1im))));
                vre[r] = n0re; vim[r] = n0im;
                vre[r1] = n1re; vim[r1] = n1im;
            }
        }
    }
}

// ---------------------------------------------------------------------------
// Main: one CTA per BATCH PAIR. Each u64 register packs (elt0, elt1) fp32.
// Layouts (3 index bits in register slot r):
//   L0: r={b11,b10,b9}  L1: r={b8,b7,b6}  L2: r={b5,b4,b3}  L3: r={b2,b1,b0}
// Exchanges double-buffered: X1,X3 -> buffer0 ; X2,X4 -> buffer1 (1 sync each).
// ---------------------------------------------------------------------------
extern __shared__ __align__(16) u64 dynsm[];

__global__ __launch_bounds__(TPB, 1) void qsim_kernel(
    const float* __restrict__ x, float* __restrict__ out) {
    __shared__ u64 sG2[NGATES * 12];
    __shared__ u64 sRed[TPB / 32];
    __shared__ float sAcc[2 * NQ];

    u64* bRe0 = dynsm;
    u64* bIm0 = dynsm + BUF;
    u64* bRe1 = dynsm + 2 * BUF;
    u64* bIm1 = dynsm + 3 * BUF;

    const int tid = threadIdx.x;
    const int bid = blockIdx.x;
    const float* xb0 = x + (size_t)(2 * bid) * DIM;
    const float* xb1 = xb0 + DIM;

    if (tid < NGATES * 12) sG2[tid] = ((const u64*)g_gates2)[tid];
    if (tid < 2 * NQ) sAcc[tid] = 0.0f;

    // ---- load both elements packed + per-element sum of squares ----
    u64 vre[RPT], vim[RPT];
    u64 ss = 0;
#pragma unroll
    for (int r = 0; r < RPT; r++) {
        int i = r * TPB + tid;
        u64 v = pk2(xb0[i], xb1[i]);
        vre[r] = v;
        vim[r] = 0;
        ss = f2fma(v, v, ss);
    }
#pragma unroll
    for (int o = 16; o; o >>= 1) ss = f2add(ss, __shfl_xor_sync(0xffffffffu, ss, o));
    if ((tid & 31) == 0) sRed[tid >> 5] = ss;
    __syncthreads();
    ss = 0;
#pragma unroll
    for (int w = 0; w < TPB / 32; w++) ss = f2add(ss, sRed[w]);
    float s0, s1; unpk2(ss, s0, s1);
    const u64 inv = pk2(rsqrtf(s0), rsqrtf(s1));
#pragma unroll
    for (int r = 0; r < RPT; r++) vre[r] = f2mul(vre[r], inv);

    // ---- loop-invariant exchange addresses (u64 element units) ----
    const int base1 = (tid & 63) * STRIDE + ((tid >> 6) & 7);                        // + r*576
    const int base2 = (((tid >> 6) << 6) | (tid & 7)) * STRIDE + ((tid >> 3) & 7);   // + r*72
    const int base3 = (tid >> 3) * (8 * STRIDE) + (tid & 7);                         // + r*9
    int addr4[RPT];
#pragma unroll
    for (int r = 0; r < RPT; r++) {
        int j = (r << 9) | tid;
#pragma unroll
        for (int g = NQ - 1; g >= 0; g--) {
            const int bc = 11 - g;
            const int bt = 11 - ((g + 1) % NQ);
            j ^= ((j >> bc) & 1) << bt;
        }
        addr4[r] = (j >> 3) * STRIDE + (j & 7);
    }

    // ---- circuit ----
#pragma unroll 1
    for (int layer = 0; layer < NLAYERS; layer++) {
        const int gbase = layer * NQ;

        apply3(vre, vim, sG2, gbase + 0);          // bits 11,10,9
        __syncthreads();                           // previous buffer1 readers done
#pragma unroll
        for (int r = 0; r < RPT; r++) {            // X1 -> buffer0
            int a = base1 + r * (64 * STRIDE);
            bRe0[a] = vre[r]; bIm0[a] = vim[r];
        }
        __syncthreads();
#pragma unroll
        for (int r = 0; r < RPT; r++) {
            int a = tid * STRIDE + r;
            vre[r] = bRe0[a]; vim[r] = bIm0[a];
        }

        apply3(vre, vim, sG2, gbase + 3);          // bits 8,7,6
#pragma unroll
        for (int r = 0; r < RPT; r++) {            // X2 -> buffer1
            int a = base2 + r * (8 * STRIDE);
            bRe1[a] = vre[r]; bIm1[a] = vim[r];
        }
        __syncthreads();
#pragma unroll
        for (int r = 0; r < RPT; r++) {
            int a = tid * STRIDE + r;
            vre[r] = bRe1[a]; vim[r] = bIm1[a];
        }

        apply3(vre, vim, sG2, gbase + 6);          // bits 5,4,3
        __syncthreads();                           // buffer0 readers done
#pragma unroll
        for (int r = 0; r < RPT; r++) {            // X3 -> buffer0
            int a = base3 + r * STRIDE;
            bRe0[a] = vre[r]; bIm0[a] = vim[r];
        }
        __syncthreads();
#pragma unroll
        for (int r = 0; r < RPT; r++) {
            int a = tid * STRIDE + r;
            vre[r] = bRe0[a]; vim[r] = bIm0[a];
        }

        apply3(vre, vim, sG2, gbase + 9);          // bits 2,1,0
        __syncthreads();                           // buffer1 readers done
#pragma unroll
        for (int r = 0; r < RPT; r++) {            // X4 -> buffer1 (sigma on read)
            int a = tid * STRIDE + r;
            bRe1[a] = vre[r]; bIm1[a] = vim[r];
        }
        __syncthreads();
#pragma unroll
        for (int r = 0; r < RPT; r++) {
            vre[r] = bRe1[addr4[r]]; vim[r] = bIm1[addr4[r]];
        }
    }

    // ---- expectations <Z_q>, both elements at once (registers only) ----
    u64 acc[NQ];
#pragma unroll
    for (int q = 0; q < NQ; q++) acc[q] = 0;
#pragma unroll
    for (int r = 0; r < RPT; r++) {
        u64 p2 = f2fma(vre[r], vre[r], f2mul(vim[r], vim[r]));
        u64 pn = p2 ^ 0x8000000080000000ULL;       // exact negation of both halves
        const int i = (r << 9) | tid;
#pragma unroll
        for (int q = 0; q < NQ; q++) {
            acc[q] = f2add(acc[q], ((i >> (11 - q)) & 1) ? pn : p2);
        }
    }
#pragma unroll
    for (int q = 0; q < NQ; q++) {
#pragma unroll
        for (int o = 16; o; o >>= 1)
            acc[q] = f2add(acc[q], __shfl_xor_sync(0xffffffffu, acc[q], o));
    }
    if ((tid & 31) == 0) {
#pragma unroll
        for (int q = 0; q < NQ; q++) {
            float p0, p1; unpk2(acc[q], p0, p1);
            atomicAdd(&sAcc[q], p0);
            atomicAdd(&sAcc[NQ + q], p1);
        }
    }
    __syncthreads();
    if (tid < NQ) {
        out[(size_t)(2 * bid) * NQ + tid] = sAcc[tid];
        out[(size_t)(2 * bid + 1) * NQ + tid] = sAcc[NQ + tid];
    }
}

extern "C" void kernel_launch(void* const* d_in, const int* in_sizes, int n_in,
                              void* d_out, int out_size) {
    const float* x = (const float*)d_in[0];       // (8192, 4096) float32
    const float* params = (const float*)d_in[1];  // (108,) float32
    float* out = (float*)d_out;                   // (8192, 12) float32
    const int batch = in_sizes[0] / DIM;
    const int smem_bytes = 4 * BUF * (int)sizeof(u64); // 147456 < 227KB cap

    cudaFuncSetAttribute(qsim_kernel, cudaFuncAttributeMaxDynamicSharedMemorySize,
                         smem_bytes);
    prep_gates<<<1, 64>>>(params);
    qsim_kernel<<<batch / 2, TPB, smem_bytes>>>(x, out);
}